// round 11
// baseline (speedup 1.0000x reference)
#include <cuda_runtime.h>
#include <cuda_bf16.h>
#include <cstdint>

#define N_NODES 100000
#define HID 128
#define NCLS 20
#define NEDGE 625000
#define TM 128
#define NTILES ((N_NODES + TM - 1) / TM)   // 782
#define GRID_F 148

// ---- smem byte offsets ----
#define SM_A      0                        // 2 bufs x (hi 16KB + lo 16KB) = 64KB
#define SM_B      (SM_A + 65536)           // hi 64KB + lo 64KB (pre-swizzled image)
#define SM_WN     (SM_B + 131072)          // fp32 [128][20] (pre-normalized)
#define SM_BS     (SM_WN + 10240)          // fp32 [128] bias
#define SM_SP     (SM_BS + 512)            // fp32 [2][128] row-sumsq halves
#define SM_HP     (SM_SP + 1024)           // fp32 [2][128][20] classifier halves
#define SM_TOTAL  (SM_HP + 20480)          // 228864 B

// Scratch (device globals: allocation-free per harness rules)
__device__ float g_sum[(size_t)N_NODES * HID];
__device__ float g_cnt[N_NODES];
__device__ int   g_is64;
__device__ __align__(16) unsigned char g_Bprep[131072];            // B bf16 hi|lo, pre-swizzled
__device__ float g_Wn[HID * NCLS];                                 // pre-normalized W_cls
// Pre-swizzled A-chunk images: per tile 64KB = [c_even 32KB][c_odd 32KB],
// each 32KB = [hi 16KB][lo 16KB], internal layout == smem A-buf image.
__device__ __align__(16) unsigned char g_Ax[(size_t)NTILES * 65536];   // x  (chunks 2,3)
__device__ __align__(16) unsigned char g_Aag[(size_t)NTILES * 65536];  // aggr (chunks 0,1)

// ============================ PTX helpers (sm_80+ ISA only) ============================
__device__ __forceinline__ uint32_t smem_u32(const void* p) {
    uint32_t a;
    asm("{ .reg .u64 t; cvta.to.shared.u64 t, %1; cvt.u32.u64 %0, t; }"
        : "=r"(a) : "l"(p));
    return a;
}
__device__ __forceinline__ void ldsm_x4(uint32_t* r, uint32_t addr) {
    asm volatile("ldmatrix.sync.aligned.m8n8.x4.shared.b16 {%0,%1,%2,%3}, [%4];"
                 : "=r"(r[0]), "=r"(r[1]), "=r"(r[2]), "=r"(r[3]) : "r"(addr));
}
__device__ __forceinline__ void ldsm_x4_t(uint32_t* r, uint32_t addr) {
    asm volatile("ldmatrix.sync.aligned.m8n8.x4.trans.shared.b16 {%0,%1,%2,%3}, [%4];"
                 : "=r"(r[0]), "=r"(r[1]), "=r"(r[2]), "=r"(r[3]) : "r"(addr));
}
__device__ __forceinline__ void mma_bf16(float* d, const uint32_t* a,
                                         uint32_t b0, uint32_t b1) {
    asm volatile("mma.sync.aligned.m16n8k16.row.col.f32.bf16.bf16.f32 "
                 "{%0,%1,%2,%3}, {%4,%5,%6,%7}, {%8,%9}, {%0,%1,%2,%3};"
                 : "+f"(d[0]), "+f"(d[1]), "+f"(d[2]), "+f"(d[3])
                 : "r"(a[0]), "r"(a[1]), "r"(a[2]), "r"(a[3]), "r"(b0), "r"(b1));
}
__device__ __forceinline__ void cp_async16(uint32_t dst, const void* src) {
    asm volatile("cp.async.cg.shared.global [%0], [%1], 16;" :: "r"(dst), "l"(src));
}
#define CP_COMMIT() asm volatile("cp.async.commit_group;" ::: "memory")
#define CP_WAIT0()  asm volatile("cp.async.wait_group 0;" ::: "memory")
#define CP_WAIT1()  asm volatile("cp.async.wait_group 1;" ::: "memory")

// split fp32 quad -> bf16 hi/lo pair, store at swizzled image offset
__device__ __forceinline__ void store_split4(char* hi_base, char* lo_base,
                                             uint32_t off, float4 v) {
    __nv_bfloat16 h0 = __float2bfloat16(v.x), h1 = __float2bfloat16(v.y);
    __nv_bfloat16 h2 = __float2bfloat16(v.z), h3 = __float2bfloat16(v.w);
    __nv_bfloat16 l0 = __float2bfloat16(v.x - __bfloat162float(h0));
    __nv_bfloat16 l1 = __float2bfloat16(v.y - __bfloat162float(h1));
    __nv_bfloat16 l2 = __float2bfloat16(v.z - __bfloat162float(h2));
    __nv_bfloat16 l3 = __float2bfloat16(v.w - __bfloat162float(h3));
    uint32_t sw = off ^ ((off >> 3) & 0x70);
    __nv_bfloat162 hp0, hp1, lp0, lp1;
    hp0.x = h0; hp0.y = h1; hp1.x = h2; hp1.y = h3;
    lp0.x = l0; lp0.y = l1; lp1.x = l2; lp1.y = l3;
    uint2 hw, lw;
    hw.x = *(uint32_t*)&hp0; hw.y = *(uint32_t*)&hp1;
    lw.x = *(uint32_t*)&lp0; lw.y = *(uint32_t*)&lp1;
    *(uint2*)(hi_base + sw) = hw;
    *(uint2*)(lo_base + sw) = lw;
}

// ============================ init: detect + prepw + Bprep + zero + x-conv ============================
#define XCONV_B0 1041
#define XCONV_N  6250                      // 100000*32/512
__global__ void __launch_bounds__(512)
k_init(const void* __restrict__ ei_raw,
       const float* __restrict__ x,
       const float* __restrict__ W_l,
       const float* __restrict__ W_r,
       const float* __restrict__ W_cls) {
    const int b = blockIdx.x;
    const int tid = threadIdx.x;

    if (b == 0) {
        if (tid < 32) {
            const long long* e64 = (const long long*)ei_raw;
            int ok = 0;
#pragma unroll
            for (int i = 0; i < 8; i++) {
                long long v = e64[tid * 8 + i];
                ok += (v >= 0 && v < N_NODES) ? 1 : 0;
            }
#pragma unroll
            for (int o = 16; o; o >>= 1) ok += __shfl_xor_sync(0xffffffffu, ok, o);
            if (tid == 0) g_is64 = (ok >= 250) ? 1 : 0;
        }
        __shared__ float nv[NCLS];
        if (tid < NCLS) {
            float ss = 0.f;
            for (int j = 0; j < HID; j++) { float v = W_cls[j * NCLS + tid]; ss += v * v; }
            nv[tid] = 1.0f / fmaxf(sqrtf(ss), 1e-12f);
        }
        __syncthreads();
        for (int i = tid; i < HID * NCLS; i += 512)
            g_Wn[i] = W_cls[i] * nv[i % NCLS];
    } else if (b <= 16) {
        // B prep: 8192 quads, k-major 256B rows, swizzle off^((off>>4)&0x70)
        int idx = (b - 1) * 512 + tid;
        int k = idx >> 5, n0 = (idx & 31) * 4;
        float4 v = (k < 128)
            ? *(const float4*)&W_l[(size_t)k * HID + n0]
            : *(const float4*)&W_r[(size_t)(k - 128) * HID + n0];
        __nv_bfloat16 h0 = __float2bfloat16(v.x), h1 = __float2bfloat16(v.y);
        __nv_bfloat16 h2 = __float2bfloat16(v.z), h3 = __float2bfloat16(v.w);
        __nv_bfloat16 l0 = __float2bfloat16(v.x - __bfloat162float(h0));
        __nv_bfloat16 l1 = __float2bfloat16(v.y - __bfloat162float(h1));
        __nv_bfloat16 l2 = __float2bfloat16(v.z - __bfloat162float(h2));
        __nv_bfloat16 l3 = __float2bfloat16(v.w - __bfloat162float(h3));
        uint32_t off = (uint32_t)(k * 256 + n0 * 2);
        uint32_t sw = off ^ ((off >> 4) & 0x70);
        __nv_bfloat162 hp0, hp1, lp0, lp1;
        hp0.x = h0; hp0.y = h1; hp1.x = h2; hp1.y = h3;
        lp0.x = l0; lp0.y = l1; lp1.x = l2; lp1.y = l3;
        uint2 hw, lw;
        hw.x = *(uint32_t*)&hp0; hw.y = *(uint32_t*)&hp1;
        lw.x = *(uint32_t*)&lp0; lw.y = *(uint32_t*)&lp1;
        *(uint2*)(g_Bprep + sw)         = hw;
        *(uint2*)(g_Bprep + 65536 + sw) = lw;
    } else if (b <= 1040) {
        // zero accumulators
        int gid = (b - 17) * 512 + tid;
        const int stride = 1024 * 512;
        float4 z = make_float4(0.f, 0.f, 0.f, 0.f);
        float4* s4 = reinterpret_cast<float4*>(g_sum);
        const int n4 = N_NODES * HID / 4;
        for (int i = gid; i < n4; i += stride) s4[i] = z;
        for (int i = gid; i < N_NODES; i += stride) g_cnt[i] = 0.f;
    } else {
        // x -> pre-swizzled bf16 hi/lo tile images (chunks 2,3)
        int idx = (b - XCONV_B0) * 512 + tid;
        if (idx >= N_NODES * 32) return;
        int n = idx >> 5, qg = idx & 31;
        float4 v = *(const float4*)&x[(size_t)n * HID + qg * 4];
        int tile = n >> 7, row = n & 127, cc = qg >> 4, ql = qg & 15;
        unsigned char* base = g_Ax + (size_t)tile * 65536 + cc * 32768;
        store_split4((char*)base, (char*)(base + 16384),
                     (uint32_t)(row * 128 + ql * 8), v);
    }
}

// ============================ scatter: 32 edges per warp ============================
__global__ void k_scatter(const float* __restrict__ x,
                          const void* __restrict__ ei_raw) {
    const int wg   = (blockIdx.x * blockDim.x + threadIdx.x) >> 5;
    const int lane = threadIdx.x & 31;
    const int base = wg * 32;
    if (base >= NEDGE) return;

    int sv = -1, dv = -1;
    const int e = base + lane;
    if (e < NEDGE) {
        if (g_is64) {
            const long long* e64 = (const long long*)ei_raw;
            long long s = e64[e], d = e64[NEDGE + e];
            sv = (s >= 0 && s < N_NODES) ? (int)s : -1;
            dv = (d >= 0 && d < N_NODES) ? (int)d : -1;
        } else {
            const int* e32 = (const int*)ei_raw;
            int s = e32[e], d = e32[NEDGE + e];
            sv = (s >= 0 && s < N_NODES) ? s : -1;
            dv = (d >= 0 && d < N_NODES) ? d : -1;
        }
    }

#pragma unroll 8
    for (int j = 0; j < 32; j++) {
        int ss = __shfl_sync(0xffffffffu, sv, j);
        int dd = __shfl_sync(0xffffffffu, dv, j);
        if (ss < 0 || dd < 0) continue;
        float4 v = *reinterpret_cast<const float4*>(&x[(size_t)ss * HID + lane * 4]);
        float* p = &g_sum[(size_t)dd * HID + lane * 4];
        asm volatile("red.global.add.v4.f32 [%0], {%1, %2, %3, %4};"
                     :: "l"(p), "f"(v.x), "f"(v.y), "f"(v.z), "f"(v.w) : "memory");
    }
    if (sv >= 0 && dv >= 0) {
        float* c = &g_cnt[dv];
        asm volatile("red.global.add.f32 [%0], %1;" :: "l"(c), "f"(1.0f) : "memory");
    }
}

// ============================ conv: aggr -> pre-swizzled bf16 images (chunks 0,1) ============================
__global__ void __launch_bounds__(512)
k_conv() {
    int idx = blockIdx.x * 512 + threadIdx.x;
    if (idx >= N_NODES * 32) return;
    int n = idx >> 5, qg = idx & 31;
    float sc = 1.0f / fmaxf(g_cnt[n], 1.0f);
    float4 t = *(const float4*)&g_sum[(size_t)n * HID + qg * 4];
    float4 v = make_float4(t.x * sc, t.y * sc, t.z * sc, t.w * sc);
    int tile = n >> 7, row = n & 127, cc = qg >> 4, ql = qg & 15;
    unsigned char* base = g_Aag + (size_t)tile * 65536 + cc * 32768;
    store_split4((char*)base, (char*)(base + 16384),
                 (uint32_t)(row * 128 + ql * 8), v);
}

// ============================ fused MMA kernel (persistent, cp.async-only A path) ============================
__device__ __forceinline__ void copy_chunk(uint32_t smem_dst, const unsigned char* src) {
    const int tid = threadIdx.x;
#pragma unroll
    for (int i = 0; i < 4; i++) {
        uint32_t off = (uint32_t)(tid + i * 512) * 16;
        cp_async16(smem_dst + off, src + off);
    }
}

__global__ void __launch_bounds__(512, 1)
k_fused(const float* __restrict__ b_l,
        float* __restrict__ out) {
    extern __shared__ __align__(1024) char smem[];
    const uint32_t sbase = smem_u32(smem);
    const int tid  = threadIdx.x;
    const int wid  = tid >> 5;
    const int lane = tid & 31;
    const int wm = wid & 7;               // warp M coordinate (8): rows wm*16..+15
    const int wn = wid >> 3;              // warp N coordinate (2): cols wn*64..+63

    float* Wn = (float*)(smem + SM_WN);
    float* bs = (float*)(smem + SM_BS);
    float* Sp = (float*)(smem + SM_SP);
    float* Hp = (float*)(smem + SM_HP);

    // ---- one-time prologue: B image + tables ----
#pragma unroll
    for (int i = 0; i < 16; i++) {
        uint32_t off = (uint32_t)(tid + i * 512) * 16;
        cp_async16(sbase + SM_B + off, g_Bprep + off);
    }
    CP_COMMIT();
    if (tid < 128) bs[tid] = b_l[tid];
    for (int i = tid; i < HID * NCLS; i += 512) Wn[i] = g_Wn[i];
    CP_WAIT0();
    __syncthreads();

    const int lane15 = lane & 15, laneh = lane >> 4;
    const int bg = lane >> 3, brr = lane & 7;

    for (int tile = blockIdx.x; tile < NTILES; tile += gridDim.x) {
        const int row0 = tile * TM;
        const size_t tb = (size_t)tile * 65536;
        const unsigned char* srcs[4] = {
            g_Aag + tb, g_Aag + tb + 32768,
            g_Ax  + tb, g_Ax  + tb + 32768
        };

        // depth-2 pipeline prologue
        copy_chunk(sbase + SM_A, srcs[0]);           CP_COMMIT();
        copy_chunk(sbase + SM_A + 32768, srcs[1]);   CP_COMMIT();
        CP_WAIT1();
        __syncthreads();

        float acc[8][4];
#pragma unroll
        for (int j = 0; j < 8; j++)
#pragma unroll
            for (int p = 0; p < 4; p++) acc[j][p] = 0.f;

#pragma unroll
        for (int c = 0; c < 4; c++) {
            const uint32_t abase = sbase + SM_A + (c & 1) * 32768;
            const uint32_t bbase = sbase + SM_B;
#pragma unroll
            for (int ks = 0; ks < 4; ks++) {
                uint32_t ah[4], al[4];
                {
                    uint32_t off = (uint32_t)((wm * 16 + lane15) * 128
                                              + ks * 32 + laneh * 16);
                    uint32_t sw = off ^ ((off >> 3) & 0x70);
                    ldsm_x4(ah, abase + sw);
                    ldsm_x4(al, abase + 16384 + sw);
                }
                uint32_t bh[4][4], bl[4][4];
                int krow = c * 64 + ks * 16 + (bg & 1) * 8 + brr;
                int nof = (bg >> 1) * 16;
#pragma unroll
                for (int j2 = 0; j2 < 4; j2++) {
                    uint32_t off = (uint32_t)(krow * 256 + wn * 128 + j2 * 32 + nof);
                    uint32_t sw = off ^ ((off >> 4) & 0x70);
                    ldsm_x4_t(bh[j2], bbase + sw);
                    ldsm_x4_t(bl[j2], bbase + 65536 + sw);
                }
#pragma unroll
                for (int j = 0; j < 8; j++) {
                    const uint32_t* Bh = &bh[j >> 1][(j & 1) * 2];
                    const uint32_t* Bl = &bl[j >> 1][(j & 1) * 2];
                    mma_bf16(acc[j], ah, Bh[0], Bh[1]);
                    mma_bf16(acc[j], al, Bh[0], Bh[1]);
                    mma_bf16(acc[j], ah, Bl[0], Bl[1]);
                }
            }
            __syncthreads();                           // all reads of this buf done
            if (c + 2 < 4) {
                copy_chunk(sbase + SM_A + (c & 1) * 32768, srcs[c + 2]);
                CP_COMMIT();
            }
            if (c < 3) {
                if (c + 2 < 4) { CP_WAIT1(); } else { CP_WAIT0(); }
                __syncthreads();                       // next chunk ready
            }
        }

        // epilogue: bias + row L2 partials + classifier partials
#pragma unroll
        for (int rr2 = 0; rr2 < 2; rr2++) {
            int row = wm * 16 + (lane >> 2) + rr2 * 8;
            float h[16];
            float ss = 0.f;
#pragma unroll
            for (int j = 0; j < 8; j++)
#pragma unroll
                for (int p = 0; p < 2; p++) {
                    int colloc = j * 8 + (lane & 3) * 2 + p;
                    float v = acc[j][rr2 * 2 + p] + bs[wn * 64 + colloc];
                    h[j * 2 + p] = v;
                    ss += v * v;
                }
            ss += __shfl_xor_sync(0xffffffffu, ss, 1);
            ss += __shfl_xor_sync(0xffffffffu, ss, 2);

            float pc[NCLS];
#pragma unroll
            for (int cc = 0; cc < NCLS; cc++) pc[cc] = 0.f;
#pragma unroll
            for (int jj = 0; jj < 16; jj++) {
                int col = wn * 64 + (jj >> 1) * 8 + (lane & 3) * 2 + (jj & 1);
                float v = h[jj];
                const float* wr = &Wn[col * NCLS];
#pragma unroll
                for (int cc = 0; cc < NCLS; cc++) pc[cc] += v * wr[cc];
            }
#pragma unroll
            for (int cc = 0; cc < NCLS; cc++) {
                pc[cc] += __shfl_xor_sync(0xffffffffu, pc[cc], 1);
                pc[cc] += __shfl_xor_sync(0xffffffffu, pc[cc], 2);
            }
            if ((lane & 3) == 0) {
                Sp[wn * 128 + row] = ss;
                float* hp = &Hp[(wn * 128 + row) * NCLS];
#pragma unroll
                for (int cc = 0; cc < NCLS; cc++) hp[cc] = pc[cc];
            }
        }
        __syncthreads();

        for (int i = tid; i < TM * NCLS; i += 512) {
            int r = i / NCLS, cc = i % NCLS;
            int gr = row0 + r;
            if (gr >= N_NODES) continue;
            float ssum = Sp[r] + Sp[128 + r];
            float rinv = 1.0f / fmaxf(sqrtf(ssum), 1e-12f);
            out[(size_t)gr * NCLS + cc] = (Hp[r * NCLS + cc] + Hp[(128 + r) * NCLS + cc]) * rinv;
        }
        // next tile's first copy targets buf0/buf1 whose readers passed the
        // epilogue __syncthreads above; Sp/Hp rewrites gated by mainloop syncs.
    }
}

// ---------------------------------------------------------------------------
extern "C" void kernel_launch(void* const* d_in, const int* in_sizes, int n_in,
                              void* d_out, int out_size) {
    const float* x     = (const float*)d_in[0];
    const void*  ei    = d_in[1];
    const float* W_l   = (const float*)d_in[2];
    const float* b_l   = (const float*)d_in[3];
    const float* W_r   = (const float*)d_in[4];
    const float* W_cls = (const float*)d_in[5];
    float*       out   = (float*)d_out;

    cudaFuncSetAttribute(k_fused, cudaFuncAttributeMaxDynamicSharedMemorySize, SM_TOTAL);

    k_init<<<XCONV_B0 + XCONV_N, 512>>>(ei, x, W_l, W_r, W_cls);

    int nwarps = (NEDGE + 31) / 32;
    int sthreads = nwarps * 32;
    k_scatter<<<(sthreads + 255) / 256, 256>>>(x, ei);

    k_conv<<<XCONV_N, 512>>>();

    k_fused<<<GRID_F, 512, SM_TOTAL>>>(b_l, out);
}